// round 10
// baseline (speedup 1.0000x reference)
#include <cuda_runtime.h>
#include <cuda_fp16.h>
#include <cstdint>
#include <cstddef>

#define BB 16
#define SS 8192
#define DD 192
#define MTOT (BB*SS)   // 131072
#define NT 512         // threads per GEMM CTA (16 warps)

// scaled-residual fp16 decomposition constants
#define S_LO   0.015625f     // s = 2^-6
#define S_HI   64.0f         // 1/s
#define ONE_MS 0.984375f     // 1 - s

// ---------------- scratch (device globals; allocations are forbidden) ----------------
__device__ float g_q[(size_t)MTOT * DD];
__device__ float g_k[(size_t)MTOT * DD];
__device__ float g_v[(size_t)MTOT * DD];
// attention output, A-side fp16 split pair packed 2/word: [row][96 words]
__device__ __align__(16) uint32_t g_a1[(size_t)MTOT * 96];
__device__ __align__(16) uint32_t g_a2[(size_t)MTOT * 96];
// weights: 4 mats (q=0,k=1,v=2,o=3) x 192 rows x 96 words, B-side split pair
__device__ __align__(16) uint32_t g_w1[4 * 192 * 96];
__device__ __align__(16) uint32_t g_w2[4 * 192 * 96];

// ---------------- helpers ----------------
__device__ __forceinline__ uint32_t packh2(float a, float b) {
    __half2 t = __floats2half2_rn(a, b);
    return reinterpret_cast<uint32_t&>(t);
}
// A-side: A1 = fp16(a); A2 = fp16((a - A1) + s*A1)
__device__ __forceinline__ void splitA(float a, float b, uint32_t& r1, uint32_t& r2) {
    float ah = __half2float(__float2half_rn(a));
    float bh = __half2float(__float2half_rn(b));
    r1 = packh2(ah, bh);
    r2 = packh2((a - ah) + S_LO * ah, (b - bh) + S_LO * bh);
}
// B-side: B1 = fp16(b); B2 = fp16((b - B1)/s + B1)
__device__ __forceinline__ void splitB(float a, float b, uint32_t& r1, uint32_t& r2) {
    float ah = __half2float(__float2half_rn(a));
    float bh = __half2float(__float2half_rn(b));
    r1 = packh2(ah, bh);
    r2 = packh2((a - ah) * S_HI + ah, (b - bh) * S_HI + bh);
}
__device__ __forceinline__ void mma16(float* c, const uint32_t a[4], uint32_t b0, uint32_t b1) {
    asm volatile("mma.sync.aligned.m16n8k16.row.col.f32.f16.f16.f32 "
        "{%0,%1,%2,%3}, {%4,%5,%6,%7}, {%8,%9}, {%0,%1,%2,%3};"
        : "+f"(c[0]), "+f"(c[1]), "+f"(c[2]), "+f"(c[3])
        : "r"(a[0]), "r"(a[1]), "r"(a[2]), "r"(a[3]), "r"(b0), "r"(b1));
}
__device__ __forceinline__ void ldsm4(uint32_t* r, uint32_t saddr) {
    asm volatile("ldmatrix.sync.aligned.m8n8.x4.shared.b16 {%0,%1,%2,%3}, [%4];"
        : "=r"(r[0]), "=r"(r[1]), "=r"(r[2]), "=r"(r[3]) : "r"(saddr));
}
__device__ __forceinline__ void ldsm2(uint32_t* r, uint32_t saddr) {
    asm volatile("ldmatrix.sync.aligned.m8n8.x2.shared.b16 {%0,%1}, [%2];"
        : "=r"(r[0]), "=r"(r[1]) : "r"(saddr));
}
__device__ __forceinline__ void cpa16(uint32_t saddr, const void* g) {
    asm volatile("cp.async.cg.shared.global [%0], [%1], 16;" :: "r"(saddr), "l"(g));
}

// smem word offsets (4-byte words), 64-row CTA, K-tile = 48 (24 words):
//   A1 [0,6400)          64 rows x stride 100 (96 used)
//   A2 [6400,12800)
//   B ring [12800,34304) 2 buffers x (B1 192x28 | B2 192x28) = 2 x 10752 words
#define A_LO_W   6400
#define B_BASE_W 12800
#define B_BUF_W  10752
#define B_HALF_W 5376
#define GEMM_SMEM (34304 * 4)   // 137216 bytes

// =====================================================================================
// split_w: pre-split all 4 weight matrices (B-side pair)
// =====================================================================================
__global__ __launch_bounds__(256) void k_split_w(
    const float* __restrict__ Wq, const float* __restrict__ Wk,
    const float* __restrict__ Wv, const float* __restrict__ Wo) {
    int f = blockIdx.x * 256 + threadIdx.x;   // < 4*9216
    int mat = f / 9216, g = f - mat * 9216;
    const float* W = (mat == 0) ? Wq : (mat == 1) ? Wk : (mat == 2) ? Wv : Wo;
    float4 v = ((const float4*)W)[g];
    uint32_t h0, l0, h1, l1;
    splitB(v.x, v.y, h0, l0);
    splitB(v.z, v.w, h1, l1);
    ((uint2*)g_w1)[f] = make_uint2(h0, h1);
    ((uint2*)g_w2)[f] = make_uint2(l0, l1);
}

// =====================================================================================
// GEMM compute step. 16 warps: grid 2(M) x 8(N), warp tile 32x24.
// Dual accumulators: out = acc2 + (1-s)*acc1.
// =====================================================================================
struct GemmCtx {
    uint32_t smb;
    int wm, wn, lr, lc, lrow, group, aoff, boff;
};

__device__ __forceinline__ void gemm_compute(
    const GemmCtx& g, float acc1[2][3][4], float acc2[2][3][4], int kt, int buf)
{
    const uint32_t bb = B_BASE_W + buf * B_BUF_W;
    #pragma unroll
    for (int c = 0; c < 3; c++) {
        uint32_t a1[2][4], a2[2][4];
        #pragma unroll
        for (int tm = 0; tm < 2; tm++) {
            uint32_t adr = g.smb + ((g.wm + tm * 16) * 100 + kt * 24 + c * 8 + g.aoff) * 4;
            ldsm4(a1[tm], adr);
            ldsm4(a2[tm], adr + A_LO_W * 4);
        }
        uint32_t b1[6], b2[6];
        {
            uint32_t adr = g.smb + (bb + g.wn * 28 + c * 8 + g.boff) * 4;
            ldsm4(b1, adr);
            ldsm4(b2, adr + B_HALF_W * 4);
            uint32_t adr2 = g.smb + (bb + (g.wn + 16 + g.lrow) * 28 + c * 8
                                     + ((g.group & 1) << 2)) * 4;
            ldsm2(b1 + 4, adr2);
            ldsm2(b2 + 4, adr2 + B_HALF_W * 4);
        }
        #pragma unroll
        for (int tm = 0; tm < 2; tm++)
            #pragma unroll
            for (int n = 0; n < 3; n++) {
                mma16(acc1[tm][n], a1[tm], b1[2 * n], b1[2 * n + 1]);
                mma16(acc2[tm][n], a2[tm], b2[2 * n], b2[2 * n + 1]);
            }
    }
}

// stage one B k-tile (48 K-values = 24 words/row, 192 rows, B1+B2)
__device__ __forceinline__ void stageB(
    uint32_t smb, int tid,
    const uint32_t* __restrict__ W1, const uint32_t* __restrict__ W2,
    int kt, int buf)
{
    #pragma unroll
    for (int i = 0; i < 5; i++) {
        int id = i * NT + tid;                  // < 2304
        if (id < 2304) {
            int half = id >= 1152;
            int j = id - (half ? 1152 : 0);
            int r = j / 6, u = j - r * 6;
            const uint32_t* src = (half ? W2 : W1) + r * 96 + kt * 24 + u * 4;
            cpa16(smb + (B_BASE_W + buf * B_BUF_W + half * B_HALF_W + r * 28 + u * 4) * 4,
                  src);
        }
    }
    asm volatile("cp.async.commit_group;");
}

// =====================================================================================
// k_qkv: CTA = 64 rows x (q,k,v). A = x rows, split inline, resident full-K.
// 12 steps: sel 0..2 x ktile 0..3, B double-buffered.
// =====================================================================================
__global__ __launch_bounds__(NT, 1) void k_qkv(
    const float* __restrict__ x,
    const float* __restrict__ bq, const float* __restrict__ bk,
    const float* __restrict__ bv)
{
    extern __shared__ __align__(16) uint32_t sm[];
    const uint32_t smb = (uint32_t)__cvta_generic_to_shared(sm);
    const int tid = threadIdx.x;
    const int warp = tid >> 5, lane = tid & 31;
    const int m0 = blockIdx.x * 64;

    GemmCtx g;
    g.smb = smb;
    g.wm = (warp >> 3) * 32;
    g.wn = (warp & 7) * 24;
    g.lr = lane >> 2;
    g.lc = lane & 3;
    g.group = lane >> 3;
    g.lrow = lane & 7;
    g.aoff = (g.lrow + ((g.group & 1) << 3)) * 100 + ((g.group >> 1) << 2);
    g.boff = (g.lrow + ((g.group >> 1) << 3)) * 28 + ((g.group & 1) << 2);

    // kick off first two B tiles (sel 0, kt 0/1)
    stageB(smb, tid, g_w1, g_w2, 0, 0);
    stageB(smb, tid, g_w1, g_w2, 1, 1);

    // stage A: x rows [m0, m0+64), fp32 -> fp16 split pair, resident, stride 100
    #pragma unroll
    for (int it = 0; it < 6; it++) {
        int id = it * NT + tid;           // < 3072 = 64*48
        int r = id / 48, f4 = id - r * 48;
        float4 v = ((const float4*)x)[(size_t)(m0 + r) * 48 + f4];
        uint32_t h0, l0, h1, l1;
        splitA(v.x, v.y, h0, l0);
        splitA(v.z, v.w, h1, l1);
        *(uint2*)(sm + r * 100 + 2 * f4)          = make_uint2(h0, h1);
        *(uint2*)(sm + A_LO_W + r * 100 + 2 * f4) = make_uint2(l0, l1);
    }

    float acc1[2][3][4], acc2[2][3][4];
    const float* biases[3] = {bq, bk, bv};

    #pragma unroll 1
    for (int s = 0; s < 12; s++) {
        const int sel = s >> 2, kt = s & 3;
        if (s < 11) asm volatile("cp.async.wait_group 1;" ::: "memory");
        else        asm volatile("cp.async.wait_group 0;" ::: "memory");
        __syncthreads();
        if (kt == 0) {
            #pragma unroll
            for (int a = 0; a < 2; a++)
                #pragma unroll
                for (int b = 0; b < 3; b++)
                    #pragma unroll
                    for (int c = 0; c < 4; c++) { acc1[a][b][c] = 0.f; acc2[a][b][c] = 0.f; }
        }
        gemm_compute(g, acc1, acc2, kt, s & 1);
        __syncthreads();
        if (s < 10) {
            int s2 = s + 2;
            stageB(smb, tid, g_w1 + (s2 >> 2) * 18432, g_w2 + (s2 >> 2) * 18432,
                   s2 & 3, s2 & 1);
        }
        if (kt == 3) {
            float* dst = (sel == 0) ? g_q : (sel == 1) ? g_k : g_v;
            const float* bias = biases[sel];
            const float scale = (sel == 0) ? 0.28867513459481287f : 1.0f;
            #pragma unroll
            for (int tm = 0; tm < 2; tm++)
                #pragma unroll
                for (int n = 0; n < 3; n++) {
                    int r = m0 + g.wm + tm * 16 + g.lr;
                    int col = g.wn + n * 8 + 2 * g.lc;
                    float b0 = __ldg(bias + col), b1 = __ldg(bias + col + 1);
                    float v0 = acc2[tm][n][0] + ONE_MS * acc1[tm][n][0];
                    float v1 = acc2[tm][n][1] + ONE_MS * acc1[tm][n][1];
                    float v2 = acc2[tm][n][2] + ONE_MS * acc1[tm][n][2];
                    float v3 = acc2[tm][n][3] + ONE_MS * acc1[tm][n][3];
                    *(float2*)(dst + (size_t)r * DD + col) =
                        make_float2((v0 + b0) * scale, (v1 + b1) * scale);
                    *(float2*)(dst + (size_t)(r + 8) * DD + col) =
                        make_float2((v2 + b0) * scale, (v3 + b1) * scale);
                }
        }
    }
}

// =====================================================================================
// k_attn: banded attention; writes A-side fp16 split pair of attn output.
// =====================================================================================
__global__ __launch_bounds__(256) void k_attn(const float* __restrict__ mask0)
{
    int g = blockIdx.x * 256 + threadIdx.x;
    int m = g >> 4;
    int h = g & 15;
    int i = m & (SS - 1);
    int b = m >> 13;

    const float* qp = g_q + (size_t)m * DD + h * 12;
    float q[12];
    #pragma unroll
    for (int j = 0; j < 3; j++) {
        float4 t = *(const float4*)(qp + 4 * j);
        q[4*j] = t.x; q[4*j+1] = t.y; q[4*j+2] = t.z; q[4*j+3] = t.w;
    }

    const float NEGINF = __int_as_float(0xff800000);
    float sc[5];
    bool val[5];
    #pragma unroll
    for (int dd = 0; dd < 5; dd++) {
        int d = dd - 2;
        int ik = i + d;
        bool v = (ik >= 0) && (ik < SS);
        val[dd] = v;
        float s = NEGINF;
        if (v) {
            const float* kp = g_k + (size_t)(m + d) * DD + h * 12;
            float a = 0.f;
            #pragma unroll
            for (int j = 0; j < 3; j++) {
                float4 t = *(const float4*)(kp + 4 * j);
                a += q[4*j] * t.x + q[4*j+1] * t.y + q[4*j+2] * t.z + q[4*j+3] * t.w;
            }
            float mk = mask0[b * SS + ik];
            s = a + ((mk != 0.f) ? -3.402823466e38f : 0.f);
        }
        sc[dd] = s;
    }
    float mx = sc[0];
    #pragma unroll
    for (int dd = 1; dd < 5; dd++) mx = fmaxf(mx, sc[dd]);
    float p[5], sum = 0.f;
    #pragma unroll
    for (int dd = 0; dd < 5; dd++) { p[dd] = __expf(sc[dd] - mx); sum += p[dd]; }
    float inv = 1.f / sum;
    if (mask0[b * SS + i] < 0.f) inv = 0.f;

    float ctx[12];
    #pragma unroll
    for (int j = 0; j < 12; j++) ctx[j] = 0.f;
    #pragma unroll
    for (int dd = 0; dd < 5; dd++) {
        if (val[dd]) {
            const float* vp = g_v + (size_t)(m + dd - 2) * DD + h * 12;
            #pragma unroll
            for (int j = 0; j < 3; j++) {
                float4 t = *(const float4*)(vp + 4 * j);
                ctx[4*j]   += p[dd] * t.x;
                ctx[4*j+1] += p[dd] * t.y;
                ctx[4*j+2] += p[dd] * t.z;
                ctx[4*j+3] += p[dd] * t.w;
            }
        }
    }
    size_t ow = (size_t)m * 96 + h * 6;
    #pragma unroll
    for (int j = 0; j < 6; j++) {
        uint32_t hw, lw;
        splitA(ctx[2*j] * inv, ctx[2*j+1] * inv, hw, lw);
        g_a1[ow + j] = hw;
        g_a2[ow + j] = lw;
    }
}

// =====================================================================================
// k_out: out = LN(attn @ Wo^T + bo + x). 64-row CTA, 4 steps, fused LN.
// =====================================================================================
__global__ __launch_bounds__(NT, 1) void k_out(
    const float* __restrict__ x, const float* __restrict__ bo,
    const float* __restrict__ lng, const float* __restrict__ lnb,
    float* __restrict__ out)
{
    extern __shared__ __align__(16) uint32_t sm[];
    const uint32_t smb = (uint32_t)__cvta_generic_to_shared(sm);
    const int tid = threadIdx.x;
    const int warp = tid >> 5, lane = tid & 31;
    const int m0 = blockIdx.x * 64;

    GemmCtx g;
    g.smb = smb;
    g.wm = (warp >> 3) * 32;
    g.wn = (warp & 7) * 24;
    g.lr = lane >> 2;
    g.lc = lane & 3;
    g.group = lane >> 3;
    g.lrow = lane & 7;
    g.aoff = (g.lrow + ((g.group & 1) << 3)) * 100 + ((g.group >> 1) << 2);
    g.boff = (g.lrow + ((g.group >> 1) << 3)) * 28 + ((g.group & 1) << 2);

    // stage A (attn, already split) via cp.async, resident
    #pragma unroll
    for (int i = 0; i < 6; i++) {
        int id = i * NT + tid;            // < 3072 = 2 halves * 64 rows * 24 chunks
        int half = id >= 1536;
        int j = id - (half ? 1536 : 0);
        int r = j / 24, u = j - r * 24;
        const uint32_t* src = (half ? g_a2 : g_a1) + (size_t)(m0 + r) * 96 + u * 4;
        cpa16(smb + (half * A_LO_W + r * 100 + u * 4) * 4, src);
    }
    asm volatile("cp.async.commit_group;");

    const uint32_t* W1 = g_w1 + 3 * 18432;
    const uint32_t* W2 = g_w2 + 3 * 18432;
    stageB(smb, tid, W1, W2, 0, 0);
    stageB(smb, tid, W1, W2, 1, 1);

    float acc1[2][3][4], acc2[2][3][4];
    #pragma unroll
    for (int a = 0; a < 2; a++)
        #pragma unroll
        for (int b = 0; b < 3; b++)
            #pragma unroll
            for (int c = 0; c < 4; c++) { acc1[a][b][c] = 0.f; acc2[a][b][c] = 0.f; }

    #pragma unroll 1
    for (int s = 0; s < 4; s++) {
        if (s < 3) asm volatile("cp.async.wait_group 1;" ::: "memory");
        else       asm volatile("cp.async.wait_group 0;" ::: "memory");
        __syncthreads();
        gemm_compute(g, acc1, acc2, s, s & 1);
        __syncthreads();
        if (s < 2) stageB(smb, tid, W1, W2, s + 2, s & 1);
    }

    // epilogue: h = (acc2 + (1-s)acc1) + bo + x -> smem (reuse A region, 64 x stride 200)
    float* sh = (float*)sm;
    #pragma unroll
    for (int tm = 0; tm < 2; tm++)
        #pragma unroll
        for (int n = 0; n < 3; n++) {
            int rl = g.wm + tm * 16 + g.lr;
            int col = g.wn + n * 8 + 2 * g.lc;
            float b0 = __ldg(bo + col), b1 = __ldg(bo + col + 1);
            float2 xv0 = *(const float2*)(x + (size_t)(m0 + rl) * DD + col);
            float2 xv1 = *(const float2*)(x + (size_t)(m0 + rl + 8) * DD + col);
            sh[rl * 200 + col]     = acc2[tm][n][0] + ONE_MS * acc1[tm][n][0] + b0 + xv0.x;
            sh[rl * 200 + col + 1] = acc2[tm][n][1] + ONE_MS * acc1[tm][n][1] + b1 + xv0.y;
            sh[(rl + 8) * 200 + col]     = acc2[tm][n][2] + ONE_MS * acc1[tm][n][2] + b0 + xv1.x;
            sh[(rl + 8) * 200 + col + 1] = acc2[tm][n][3] + ONE_MS * acc1[tm][n][3] + b1 + xv1.y;
        }
    __syncthreads();

    #pragma unroll 1
    for (int it = 0; it < 4; it++) {
        int r = it * 16 + warp;
        float v[6]; float sum = 0.f, ssq = 0.f;
        #pragma unroll
        for (int j = 0; j < 6; j++) {
            v[j] = sh[r * 200 + j * 32 + lane];
            sum += v[j];
            ssq += v[j] * v[j];
        }
        #pragma unroll
        for (int o = 16; o > 0; o >>= 1) {
            sum += __shfl_xor_sync(0xffffffffu, sum, o);
            ssq += __shfl_xor_sync(0xffffffffu, ssq, o);
        }
        float mu  = sum * (1.f / 192.f);
        float var = ssq * (1.f / 192.f) - mu * mu;
        float rs  = rsqrtf(fmaxf(var, 0.f) + 1e-12f);
        #pragma unroll
        for (int j = 0; j < 6; j++) {
            int c = j * 32 + lane;
            out[(size_t)(m0 + r) * DD + c] = (v[j] - mu) * rs * __ldg(lng + c) + __ldg(lnb + c);
        }
    }
}

// =====================================================================================
extern "C" void kernel_launch(void* const* d_in, const int* in_sizes, int n_in,
                              void* d_out, int out_size)
{
    const float* x    = (const float*)d_in[0];
    const float* mask0= (const float*)d_in[1];
    const float* Wq   = (const float*)d_in[2];
    const float* bq   = (const float*)d_in[3];
    const float* Wk   = (const float*)d_in[4];
    const float* bk   = (const float*)d_in[5];
    const float* Wv   = (const float*)d_in[6];
    const float* bv   = (const float*)d_in[7];
    const float* Wo   = (const float*)d_in[8];
    const float* bo   = (const float*)d_in[9];
    const float* lng  = (const float*)d_in[10];
    const float* lnb  = (const float*)d_in[11];
    float* out = (float*)d_out;

    cudaFuncSetAttribute(k_qkv, cudaFuncAttributeMaxDynamicSharedMemorySize, GEMM_SMEM);
    cudaFuncSetAttribute(k_out, cudaFuncAttributeMaxDynamicSharedMemorySize, GEMM_SMEM);

    k_split_w<<<144, 256>>>(Wq, Wk, Wv, Wo);
    k_qkv<<<MTOT / 64, NT, GEMM_SMEM>>>(x, bq, bk, bv);
    k_attn<<<(MTOT * 16) / 256, 256>>>(mask0);
    k_out<<<MTOT / 64, NT, GEMM_SMEM>>>(x, bo, lng, lnb, out);
}

// round 13
// speedup vs baseline: 1.0261x; 1.0261x over previous
#include <cuda_runtime.h>
#include <cuda_fp16.h>
#include <cstdint>
#include <cstddef>

#define BB 16
#define SS 8192
#define DD 192
#define MTOT (BB*SS)   // 131072
#define NT 256         // threads per GEMM CTA (8 warps)

// scaled-residual fp16 decomposition constants (validated R10)
#define S_LO   0.015625f     // s = 2^-6
#define S_HI   64.0f         // 1/s
#define ONE_MS 0.984375f     // 1 - s

// ---------------- scratch (device globals; allocations are forbidden) ----------------
__device__ float g_q[(size_t)MTOT * DD];
__device__ float g_k[(size_t)MTOT * DD];
__device__ float g_v[(size_t)MTOT * DD];
// attention output, A-side fp16 split pair packed 2/word: [row][96 words]
__device__ __align__(16) uint32_t g_a1[(size_t)MTOT * 96];
__device__ __align__(16) uint32_t g_a2[(size_t)MTOT * 96];
// weights: 4 mats (q=0,k=1,v=2,o=3) x 192 rows x 96 words, B-side split pair
__device__ __align__(16) uint32_t g_w1[4 * 192 * 96];
__device__ __align__(16) uint32_t g_w2[4 * 192 * 96];

// ---------------- helpers ----------------
__device__ __forceinline__ uint32_t packh2(float a, float b) {
    __half2 t = __floats2half2_rn(a, b);
    return reinterpret_cast<uint32_t&>(t);
}
// A-side: A1 = fp16(a); A2 = fp16((a - A1) + s*A1)
__device__ __forceinline__ void splitA(float a, float b, uint32_t& r1, uint32_t& r2) {
    float ah = __half2float(__float2half_rn(a));
    float bh = __half2float(__float2half_rn(b));
    r1 = packh2(ah, bh);
    r2 = packh2((a - ah) + S_LO * ah, (b - bh) + S_LO * bh);
}
// B-side: B1 = fp16(b); B2 = fp16((b - B1)/s + B1)
__device__ __forceinline__ void splitB(float a, float b, uint32_t& r1, uint32_t& r2) {
    float ah = __half2float(__float2half_rn(a));
    float bh = __half2float(__float2half_rn(b));
    r1 = packh2(ah, bh);
    r2 = packh2((a - ah) * S_HI + ah, (b - bh) * S_HI + bh);
}
__device__ __forceinline__ void mma16(float* c, const uint32_t a[4], uint32_t b0, uint32_t b1) {
    asm volatile("mma.sync.aligned.m16n8k16.row.col.f32.f16.f16.f32 "
        "{%0,%1,%2,%3}, {%4,%5,%6,%7}, {%8,%9}, {%0,%1,%2,%3};"
        : "+f"(c[0]), "+f"(c[1]), "+f"(c[2]), "+f"(c[3])
        : "r"(a[0]), "r"(a[1]), "r"(a[2]), "r"(a[3]), "r"(b0), "r"(b1));
}
__device__ __forceinline__ void ldsm4(uint32_t* r, uint32_t saddr) {
    asm volatile("ldmatrix.sync.aligned.m8n8.x4.shared.b16 {%0,%1,%2,%3}, [%4];"
        : "=r"(r[0]), "=r"(r[1]), "=r"(r[2]), "=r"(r[3]) : "r"(saddr));
}
__device__ __forceinline__ void cpa16(uint32_t saddr, const void* g) {
    asm volatile("cp.async.cg.shared.global [%0], [%1], 16;" :: "r"(saddr), "l"(g));
}

// smem word offsets (4-byte words), 64-row CTA, K-tile = 48 (24 words):
//   A1 [0,6400)          64 rows x stride 100 (96 used)
//   A2 [6400,12800)
//   B ring [12800,45056) 3 buffers x (B1 192x28 | B2 192x28) = 3 x 10752 words
#define A_LO_W   6400
#define B_BASE_W 12800
#define B_BUF_W  10752
#define B_HALF_W 5376
#define GEMM_SMEM (45056 * 4)   // 180224 bytes

// =====================================================================================
// split_w: pre-split all 4 weight matrices (B-side pair)
// =====================================================================================
__global__ __launch_bounds__(256) void k_split_w(
    const float* __restrict__ Wq, const float* __restrict__ Wk,
    const float* __restrict__ Wv, const float* __restrict__ Wo) {
    int f = blockIdx.x * 256 + threadIdx.x;   // < 4*9216
    int mat = f / 9216, g = f - mat * 9216;
    const float* W = (mat == 0) ? Wq : (mat == 1) ? Wk : (mat == 2) ? Wv : Wo;
    float4 v = ((const float4*)W)[g];
    uint32_t h0, l0, h1, l1;
    splitB(v.x, v.y, h0, l0);
    splitB(v.z, v.w, h1, l1);
    ((uint2*)g_w1)[f] = make_uint2(h0, h1);
    ((uint2*)g_w2)[f] = make_uint2(l0, l1);
}

// =====================================================================================
// GEMM compute step. 8 warps: grid 2(M) x 4(N), warp tile 32x48, all-ldsm4.
// Dual accumulators: out = acc2 + (1-s)*acc1.
// =====================================================================================
struct GemmCtx {
    uint32_t smb;
    int wm, wn, lr, lc, aoff, boff;
};

__device__ __forceinline__ void gemm_compute(
    const GemmCtx& g, float acc1[2][6][4], float acc2[2][6][4], int kt, int buf)
{
    const uint32_t bb = B_BASE_W + buf * B_BUF_W;
    #pragma unroll
    for (int c = 0; c < 3; c++) {
        uint32_t a1[2][4], a2[2][4];
        #pragma unroll
        for (int tm = 0; tm < 2; tm++) {
            uint32_t adr = g.smb + ((g.wm + tm * 16) * 100 + kt * 24 + c * 8 + g.aoff) * 4;
            ldsm4(a1[tm], adr);
            ldsm4(a2[tm], adr + A_LO_W * 4);
        }
        uint32_t b1[3][4], b2[3][4];
        #pragma unroll
        for (int jp = 0; jp < 3; jp++) {
            uint32_t adr = g.smb + (bb + (g.wn + jp * 16) * 28 + c * 8 + g.boff) * 4;
            ldsm4(b1[jp], adr);
            ldsm4(b2[jp], adr + B_HALF_W * 4);
        }
        #pragma unroll
        for (int tm = 0; tm < 2; tm++)
            #pragma unroll
            for (int jp = 0; jp < 3; jp++) {
                mma16(acc1[tm][2*jp],   a1[tm], b1[jp][0], b1[jp][1]);
                mma16(acc1[tm][2*jp+1], a1[tm], b1[jp][2], b1[jp][3]);
                mma16(acc2[tm][2*jp],   a2[tm], b2[jp][0], b2[jp][1]);
                mma16(acc2[tm][2*jp+1], a2[tm], b2[jp][2], b2[jp][3]);
            }
    }
}

// stage one B k-tile (48 K-values = 24 words/row, 192 rows, B1+B2)
__device__ __forceinline__ void stageB(
    uint32_t smb, int tid,
    const uint32_t* __restrict__ W1, const uint32_t* __restrict__ W2,
    int kt, int buf)
{
    #pragma unroll
    for (int i = 0; i < 9; i++) {
        int id = i * NT + tid;                  // < 2304
        int half = id >= 1152;
        int j = id - (half ? 1152 : 0);
        int r = j / 6, u = j - r * 6;
        const uint32_t* src = (half ? W2 : W1) + r * 96 + kt * 24 + u * 4;
        cpa16(smb + (B_BASE_W + buf * B_BUF_W + half * B_HALF_W + r * 28 + u * 4) * 4, src);
    }
    asm volatile("cp.async.commit_group;");
}

// =====================================================================================
// k_qkv: CTA = 64 rows x (q,k,v). A = x rows, split inline, resident full-K.
// 12 steps: sel 0..2 x ktile 0..3, B triple-buffered (2 staging groups in flight).
// =====================================================================================
__global__ __launch_bounds__(NT, 1) void k_qkv(
    const float* __restrict__ x,
    const float* __restrict__ bq, const float* __restrict__ bk,
    const float* __restrict__ bv)
{
    extern __shared__ __align__(16) uint32_t sm[];
    const uint32_t smb = (uint32_t)__cvta_generic_to_shared(sm);
    const int tid = threadIdx.x;
    const int warp = tid >> 5, lane = tid & 31;
    const int m0 = blockIdx.x * 64;
    const int group = lane >> 3, lrow = lane & 7;

    GemmCtx g;
    g.smb = smb;
    g.wm = (warp >> 2) * 32;
    g.wn = (warp & 3) * 48;
    g.lr = lane >> 2;
    g.lc = lane & 3;
    g.aoff = (lrow + ((group & 1) << 3)) * 100 + ((group >> 1) << 2);
    g.boff = (lrow + ((group >> 1) << 3)) * 28 + ((group & 1) << 2);

    // kick off first three B tiles (sel 0: kt 0/1/2)
    stageB(smb, tid, g_w1, g_w2, 0, 0);
    stageB(smb, tid, g_w1, g_w2, 1, 1);
    stageB(smb, tid, g_w1, g_w2, 2, 2);

    // stage A: x rows [m0, m0+64), fp32 -> fp16 split pair, resident, stride 100
    #pragma unroll
    for (int it = 0; it < 12; it++) {
        int id = it * NT + tid;           // < 3072 = 64*48
        int r = id / 48, f4 = id - r * 48;
        float4 v = ((const float4*)x)[(size_t)(m0 + r) * 48 + f4];
        uint32_t h0, l0, h1, l1;
        splitA(v.x, v.y, h0, l0);
        splitA(v.z, v.w, h1, l1);
        *(uint2*)(sm + r * 100 + 2 * f4)          = make_uint2(h0, h1);
        *(uint2*)(sm + A_LO_W + r * 100 + 2 * f4) = make_uint2(l0, l1);
    }

    float acc1[2][6][4], acc2[2][6][4];
    const float* biases[3] = {bq, bk, bv};

    #pragma unroll 1
    for (int s = 0; s < 12; s++) {
        const int sel = s >> 2, kt = s & 3;
        if (s < 10)      asm volatile("cp.async.wait_group 2;" ::: "memory");
        else if (s < 11) asm volatile("cp.async.wait_group 1;" ::: "memory");
        else             asm volatile("cp.async.wait_group 0;" ::: "memory");
        __syncthreads();
        if (kt == 0) {
            #pragma unroll
            for (int a = 0; a < 2; a++)
                #pragma unroll
                for (int b = 0; b < 6; b++)
                    #pragma unroll
                    for (int c = 0; c < 4; c++) { acc1[a][b][c] = 0.f; acc2[a][b][c] = 0.f; }
        }
        gemm_compute(g, acc1, acc2, kt, s % 3);
        __syncthreads();
        if (s < 9) {
            int s2 = s + 3;
            stageB(smb, tid, g_w1 + (s2 >> 2) * 18432, g_w2 + (s2 >> 2) * 18432,
                   s2 & 3, s2 % 3);
        }
        if (kt == 3) {
            float* dst = (sel == 0) ? g_q : (sel == 1) ? g_k : g_v;
            const float* bias = biases[sel];
            const float scale = (sel == 0) ? 0.28867513459481287f : 1.0f;
            #pragma unroll
            for (int tm = 0; tm < 2; tm++)
                #pragma unroll
                for (int n = 0; n < 6; n++) {
                    int r = m0 + g.wm + tm * 16 + g.lr;
                    int col = g.wn + n * 8 + 2 * g.lc;
                    float b0 = __ldg(bias + col), b1 = __ldg(bias + col + 1);
                    float v0 = acc2[tm][n][0] + ONE_MS * acc1[tm][n][0];
                    float v1 = acc2[tm][n][1] + ONE_MS * acc1[tm][n][1];
                    float v2 = acc2[tm][n][2] + ONE_MS * acc1[tm][n][2];
                    float v3 = acc2[tm][n][3] + ONE_MS * acc1[tm][n][3];
                    *(float2*)(dst + (size_t)r * DD + col) =
                        make_float2((v0 + b0) * scale, (v1 + b1) * scale);
                    *(float2*)(dst + (size_t)(r + 8) * DD + col) =
                        make_float2((v2 + b0) * scale, (v3 + b1) * scale);
                }
        }
    }
}

// =====================================================================================
// k_attn: banded attention; writes A-side fp16 split pair of attn output.
// =====================================================================================
__global__ __launch_bounds__(256) void k_attn(const float* __restrict__ mask0)
{
    int g = blockIdx.x * 256 + threadIdx.x;
    int m = g >> 4;
    int h = g & 15;
    int i = m & (SS - 1);
    int b = m >> 13;

    const float* qp = g_q + (size_t)m * DD + h * 12;
    float q[12];
    #pragma unroll
    for (int j = 0; j < 3; j++) {
        float4 t = *(const float4*)(qp + 4 * j);
        q[4*j] = t.x; q[4*j+1] = t.y; q[4*j+2] = t.z; q[4*j+3] = t.w;
    }

    const float NEGINF = __int_as_float(0xff800000);
    float sc[5];
    bool val[5];
    #pragma unroll
    for (int dd = 0; dd < 5; dd++) {
        int d = dd - 2;
        int ik = i + d;
        bool v = (ik >= 0) && (ik < SS);
        val[dd] = v;
        float s = NEGINF;
        if (v) {
            const float* kp = g_k + (size_t)(m + d) * DD + h * 12;
            float a = 0.f;
            #pragma unroll
            for (int j = 0; j < 3; j++) {
                float4 t = *(const float4*)(kp + 4 * j);
                a += q[4*j] * t.x + q[4*j+1] * t.y + q[4*j+2] * t.z + q[4*j+3] * t.w;
            }
            float mk = mask0[b * SS + ik];
            s = a + ((mk != 0.f) ? -3.402823466e38f : 0.f);
        }
        sc[dd] = s;
    }
    float mx = sc[0];
    #pragma unroll
    for (int dd = 1; dd < 5; dd++) mx = fmaxf(mx, sc[dd]);
    float p[5], sum = 0.f;
    #pragma unroll
    for (int dd = 0; dd < 5; dd++) { p[dd] = __expf(sc[dd] - mx); sum += p[dd]; }
    float inv = 1.f / sum;
    if (mask0[b * SS + i] < 0.f) inv = 0.f;

    float ctx[12];
    #pragma unroll
    for (int j = 0; j < 12; j++) ctx[j] = 0.f;
    #pragma unroll
    for (int dd = 0; dd < 5; dd++) {
        if (val[dd]) {
            const float* vp = g_v + (size_t)(m + dd - 2) * DD + h * 12;
            #pragma unroll
            for (int j = 0; j < 3; j++) {
                float4 t = *(const float4*)(vp + 4 * j);
                ctx[4*j]   += p[dd] * t.x;
                ctx[4*j+1] += p[dd] * t.y;
                ctx[4*j+2] += p[dd] * t.z;
                ctx[4*j+3] += p[dd] * t.w;
            }
        }
    }
    size_t ow = (size_t)m * 96 + h * 6;
    #pragma unroll
    for (int j = 0; j < 6; j++) {
        uint32_t hw, lw;
        splitA(ctx[2*j] * inv, ctx[2*j+1] * inv, hw, lw);
        g_a1[ow + j] = hw;
        g_a2[ow + j] = lw;
    }
}

// =====================================================================================
// k_out: out = LN(attn @ Wo^T + bo + x). 64-row CTA, 4 steps, 3-deep ring, fused LN.
// =====================================================================================
__global__ __launch_bounds__(NT, 1) void k_out(
    const float* __restrict__ x, const float* __restrict__ bo,
    const float* __restrict__ lng, const float* __restrict__ lnb,
    float* __restrict__ out)
{
    extern __shared__ __align__(16) uint32_t sm[];
    const uint32_t smb = (uint32_t)__cvta_generic_to_shared(sm);
    const int tid = threadIdx.x;
    const int warp = tid >> 5, lane = tid & 31;
    const int m0 = blockIdx.x * 64;
    const int group = lane >> 3, lrow = lane & 7;

    GemmCtx g;
    g.smb = smb;
    g.wm = (warp >> 2) * 32;
    g.wn = (warp & 3) * 48;
    g.lr = lane >> 2;
    g.lc = lane & 3;
    g.aoff = (lrow + ((group & 1) << 3)) * 100 + ((group >> 1) << 2);
    g.boff = (lrow + ((group >> 1) << 3)) * 28 + ((group & 1) << 2);

    // stage A (attn, already split) via cp.async, resident
    #pragma unroll
    for (int i = 0; i < 12; i++) {
        int id = i * NT + tid;            // < 3072 = 2 halves * 64 rows * 24 chunks
        int half = id >= 1536;
        int j = id - (half ? 1536 : 0);
        int r = j / 24, u = j - r * 24;
        const uint32_t* src = (half ? g_a2 : g_a1) + (size_t)(m0 + r) * 96 + u * 4;
        cpa16(smb + (half * A_LO_W + r * 100 + u * 4) * 4, src);
    }
    asm volatile("cp.async.commit_group;");

    const uint32_t* W1 = g_w1 + 3 * 18432;
    const uint32_t* W2 = g_w2 + 3 * 18432;
    stageB(smb, tid, W1, W2, 0, 0);
    stageB(smb, tid, W1, W2, 1, 1);
    stageB(smb, tid, W1, W2, 2, 2);

    float acc1[2][6][4], acc2[2][6][4];
    #pragma unroll
    for (int a = 0; a < 2; a++)
        #pragma unroll
        for (int b = 0; b < 6; b++)
            #pragma unroll
            for (int c = 0; c < 4; c++) { acc1[a][b][c] = 0.f; acc2[a][b][c] = 0.f; }

    #pragma unroll 1
    for (int s = 0; s < 4; s++) {
        if (s < 2)      asm volatile("cp.async.wait_group 2;" ::: "memory");
        else if (s < 3) asm volatile("cp.async.wait_group 1;" ::: "memory");
        else            asm volatile("cp.async.wait_group 0;" ::: "memory");
        __syncthreads();
        gemm_compute(g, acc1, acc2, s, s % 3);
        __syncthreads();
        if (s < 1) stageB(smb, tid, W1, W2, s + 3, (s + 3) % 3);
    }

    // epilogue: h = (acc2 + (1-s)acc1) + bo + x -> smem (reuse A region, 64 x stride 200)
    float* sh = (float*)sm;
    #pragma unroll
    for (int tm = 0; tm < 2; tm++)
        #pragma unroll
        for (int n = 0; n < 6; n++) {
            int rl = g.wm + tm * 16 + g.lr;
            int col = g.wn + n * 8 + 2 * g.lc;
            float b0 = __ldg(bo + col), b1 = __ldg(bo + col + 1);
            float2 xv0 = *(const float2*)(x + (size_t)(m0 + rl) * DD + col);
            float2 xv1 = *(const float2*)(x + (size_t)(m0 + rl + 8) * DD + col);
            sh[rl * 200 + col]     = acc2[tm][n][0] + ONE_MS * acc1[tm][n][0] + b0 + xv0.x;
            sh[rl * 200 + col + 1] = acc2[tm][n][1] + ONE_MS * acc1[tm][n][1] + b1 + xv0.y;
            sh[(rl + 8) * 200 + col]     = acc2[tm][n][2] + ONE_MS * acc1[tm][n][2] + b0 + xv1.x;
            sh[(rl + 8) * 200 + col + 1] = acc2[tm][n][3] + ONE_MS * acc1[tm][n][3] + b1 + xv1.y;
        }
    __syncthreads();

    #pragma unroll 1
    for (int it = 0; it < 8; it++) {
        int r = it * 8 + warp;
        float v[6]; float sum = 0.f, ssq = 0.f;
        #pragma unroll
        for (int j = 0; j < 6; j++) {
            v[j] = sh[r * 200 + j * 32 + lane];
            sum += v[j];
            ssq += v[j] * v[j];
        }
        #pragma unroll
        for (int o = 16; o > 0; o >>= 1) {
            sum += __shfl_xor_sync(0xffffffffu, sum, o);
            ssq += __shfl_xor_sync(0xffffffffu, ssq, o);
        }
        float mu  = sum * (1.f / 192.f);
        float var = ssq * (1.f / 192.f) - mu * mu;
        float rs  = rsqrtf(fmaxf(var, 0.f) + 1e-12f);
        #pragma unroll
        for (int j = 0; j < 6; j++) {
            int c = j * 32 + lane;
            out[(size_t)(m0 + r) * DD + c] = (v[j] - mu) * rs * __ldg(lng + c) + __ldg(lnb + c);
        }
    }
}

// =====================================================================================
extern "C" void kernel_launch(void* const* d_in, const int* in_sizes, int n_in,
                              void* d_out, int out_size)
{
    const float* x    = (const float*)d_in[0];
    const float* mask0= (const float*)d_in[1];
    const float* Wq   = (const float*)d_in[2];
    const float* bq   = (const float*)d_in[3];
    const float* Wk   = (const float*)d_in[4];
    const float* bk   = (const float*)d_in[5];
    const float* Wv   = (const float*)d_in[6];
    const float* bv   = (const float*)d_in[7];
    const float* Wo   = (const float*)d_in[8];
    const float* bo   = (const float*)d_in[9];
    const float* lng  = (const float*)d_in[10];
    const float* lnb  = (const float*)d_in[11];
    float* out = (float*)d_out;

    cudaFuncSetAttribute(k_qkv, cudaFuncAttributeMaxDynamicSharedMemorySize, GEMM_SMEM);
    cudaFuncSetAttribute(k_out, cudaFuncAttributeMaxDynamicSharedMemorySize, GEMM_SMEM);

    k_split_w<<<144, 256>>>(Wq, Wk, Wv, Wo);
    k_qkv<<<MTOT / 64, NT, GEMM_SMEM>>>(x, bq, bk, bv);
    k_attn<<<(MTOT * 16) / 256, 256>>>(mask0);
    k_out<<<MTOT / 64, NT, GEMM_SMEM>>>(x, bo, lng, lnb, out);
}

// round 14
// speedup vs baseline: 1.3239x; 1.2903x over previous
#include <cuda_runtime.h>
#include <cuda_bf16.h>
#include <cstdint>
#include <cstddef>

#define BB 16
#define SS 8192
#define DD 192
#define MTOT (BB*SS)   // 131072
#define NT 256         // 8 warps
#define NCTA 152       // persistent grid (GB300: 152 SMs)
#define NTILES 4096    // 32-row tiles

// ---------------- scratch (device globals; allocations are forbidden) ----------------
__device__ float g_q[(size_t)MTOT * DD];
__device__ float g_k[(size_t)MTOT * DD];
__device__ float g_v[(size_t)MTOT * DD];
// attention output, bf16 hi/lo pair packed 2/word: [row][96 words]
__device__ __align__(16) uint32_t g_ah[(size_t)MTOT * 96];
__device__ __align__(16) uint32_t g_al[(size_t)MTOT * 96];
// weights: 4 mats (q=0,k=1,v=2,o=3) x 192 rows x 96 words, bf16 hi/lo
__device__ __align__(16) uint32_t g_wh[4 * 192 * 96];
__device__ __align__(16) uint32_t g_wl[4 * 192 * 96];

// ---------------- helpers ----------------
__device__ __forceinline__ uint32_t pack2(float a, float b) {
    __nv_bfloat162 t = __floats2bfloat162_rn(a, b);
    return reinterpret_cast<uint32_t&>(t);
}
__device__ __forceinline__ void split2(float a, float b, uint32_t& h, uint32_t& l) {
    float ah = __bfloat162float(__float2bfloat16_rn(a));
    float bh = __bfloat162float(__float2bfloat16_rn(b));
    h = pack2(ah, bh);
    l = pack2(a - ah, b - bh);
}
__device__ __forceinline__ void mma16(float* c, const uint32_t a[4], uint32_t b0, uint32_t b1) {
    asm volatile("mma.sync.aligned.m16n8k16.row.col.f32.bf16.bf16.f32 "
        "{%0,%1,%2,%3}, {%4,%5,%6,%7}, {%8,%9}, {%0,%1,%2,%3};"
        : "+f"(c[0]), "+f"(c[1]), "+f"(c[2]), "+f"(c[3])
        : "r"(a[0]), "r"(a[1]), "r"(a[2]), "r"(a[3]), "r"(b0), "r"(b1));
}
__device__ __forceinline__ void ldsm4(uint32_t* r, uint32_t saddr) {
    asm volatile("ldmatrix.sync.aligned.m8n8.x4.shared.b16 {%0,%1,%2,%3}, [%4];"
        : "=r"(r[0]), "=r"(r[1]), "=r"(r[2]), "=r"(r[3]) : "r"(saddr));
}
__device__ __forceinline__ void cpa16(uint32_t saddr, const void* g) {
    asm volatile("cp.async.cg.shared.global [%0], [%1], 16;" :: "r"(saddr), "l"(g));
}

// smem word map (4-byte words):
//   A buffers: buf b at b*6400: hi [0,3200), lo [3200,6400)   (32 rows x stride 100)
//   B resident: hi at 12800 (192 x stride 100), lo at 32000
//   red (k_out LN): at 51200, 32 rows x 4 nwarps x 2 floats = 256 words
#define A_BUF_W  6400
#define B_HI_W   12800
#define B_LO_W   32000
#define RED_W    51200
#define QKV_SMEM (51200 * 4)   // 204800 B
#define OUT_SMEM (51456 * 4)   // 205824 B

__device__ __forceinline__ void tile_range(int c, int& start, int& count) {
    const int base = NTILES / NCTA;            // 26
    const int rem  = NTILES - base * NCTA;     // 144
    count = base + (c < rem ? 1 : 0);
    start = c * base + (c < rem ? c : rem);
}

// =====================================================================================
// split_w: pre-split all 4 weight matrices into bf16 hi/lo
// =====================================================================================
__global__ __launch_bounds__(256) void k_split_w(
    const float* __restrict__ Wq, const float* __restrict__ Wk,
    const float* __restrict__ Wv, const float* __restrict__ Wo) {
    int f = blockIdx.x * 256 + threadIdx.x;   // < 4*9216
    int mat = f / 9216, g = f - mat * 9216;
    const float* W = (mat == 0) ? Wq : (mat == 1) ? Wk : (mat == 2) ? Wv : Wo;
    float4 v = ((const float4*)W)[g];
    uint32_t h0, l0, h1, l1;
    split2(v.x, v.y, h0, l0);
    split2(v.z, v.w, h1, l1);
    ((uint2*)g_wh)[f] = make_uint2(h0, h1);
    ((uint2*)g_wl)[f] = make_uint2(l0, l1);
}

// =====================================================================================
// Core compute: one 32-row tile, full K=192, B resident. Warp grid 2(M) x 4(N),
// warp tile 16 x 48, bf16 3-term. acc[6][4] zeroed by caller.
// =====================================================================================
__device__ __forceinline__ void compute_tile(
    uint32_t smb, int buf, int wm, int wn, int aoff, int boff, float acc[6][4])
{
    const uint32_t abase = smb + (buf * A_BUF_W + wm * 100 + aoff) * 4;
    #pragma unroll
    for (int c = 0; c < 12; c++) {
        uint32_t ah[4], al[4];
        uint32_t aa = abase + c * 8 * 4;
        ldsm4(ah, aa);
        ldsm4(al, aa + 3200 * 4);
        uint32_t bh[3][4], bl[3][4];
        #pragma unroll
        for (int jp = 0; jp < 3; jp++) {
            uint32_t ba = smb + (B_HI_W + (wn + jp * 16) * 100 + c * 8 + boff) * 4;
            ldsm4(bh[jp], ba);
            ldsm4(bl[jp], ba + 19200 * 4);
        }
        #pragma unroll
        for (int jp = 0; jp < 3; jp++) {
            mma16(acc[2*jp],   ah, bl[jp][0], bl[jp][1]);
            mma16(acc[2*jp],   al, bh[jp][0], bh[jp][1]);
            mma16(acc[2*jp],   ah, bh[jp][0], bh[jp][1]);
            mma16(acc[2*jp+1], ah, bl[jp][2], bl[jp][3]);
            mma16(acc[2*jp+1], al, bh[jp][2], bh[jp][3]);
            mma16(acc[2*jp+1], ah, bh[jp][2], bh[jp][3]);
        }
    }
}

// stage full-K resident B (one weight matrix, hi+lo) via cp.async; 36 cpa16/thread
__device__ __forceinline__ void stage_B_resident(
    uint32_t smb, int tid, const uint32_t* __restrict__ Wh, const uint32_t* __restrict__ Wl)
{
    #pragma unroll
    for (int i = 0; i < 36; i++) {
        int id = i * NT + tid;                  // < 9216
        int half = id >= 4608;
        int j = id - (half ? 4608 : 0);
        int r = j / 24, u = j - r * 24;
        const uint32_t* src = (half ? Wl : Wh) + r * 96 + u * 4;
        cpa16(smb + ((half ? B_LO_W : B_HI_W) + r * 100 + u * 4) * 4, src);
    }
    asm volatile("cp.async.commit_group;");
}

// =====================================================================================
// k_qkv: persistent. B(sel) resident; loop sels outer, 32-row A tiles inner.
// A: x fp32 LDG-prefetched to regs, split inline, double-buffered in smem.
// =====================================================================================
__global__ __launch_bounds__(NT, 1) void k_qkv(
    const float* __restrict__ x,
    const float* __restrict__ bq, const float* __restrict__ bk,
    const float* __restrict__ bv)
{
    extern __shared__ __align__(16) uint32_t sm[];
    const uint32_t smb = (uint32_t)__cvta_generic_to_shared(sm);
    const int tid = threadIdx.x;
    const int warp = tid >> 5, lane = tid & 31;
    const int group = lane >> 3, lrow = lane & 7;
    const int wm = (warp >> 2) * 16, wn = (warp & 3) * 48;
    const int lr = lane >> 2, lc = lane & 3;
    const int aoff = (lrow + ((group & 1) << 3)) * 100 + ((group >> 1) << 2);
    const int boff = (lrow + ((group >> 1) << 3)) * 100 + ((group & 1) << 2);

    int start, count;
    tile_range(blockIdx.x, start, count);

    #pragma unroll 1
    for (int sel = 0; sel < 3; sel++) {
        __syncthreads();   // previous sel's compute fully done before B overwrite
        stage_B_resident(smb, tid,
                         g_wh + sel * 18432, g_wl + sel * 18432);

        const float* bias = (sel == 0) ? bq : (sel == 1) ? bk : bv;
        const float scale = (sel == 0) ? 0.28867513459481287f : 1.0f;
        float* dst = (sel == 0) ? g_q : (sel == 1) ? g_k : g_v;
        float b0r[6], b1r[6];
        #pragma unroll
        for (int n = 0; n < 6; n++) {
            int col = wn + n * 8 + 2 * lc;
            b0r[n] = __ldg(bias + col);
            b1r[n] = __ldg(bias + col + 1);
        }

        // A prologue: LDG tile0 to regs, split, STS -> buf0
        float4 pf[6];
        {
            int m0 = start * 32;
            #pragma unroll
            for (int j = 0; j < 6; j++) {
                int id = j * NT + tid;
                int r = id / 48, f4 = id - r * 48;
                pf[j] = ((const float4*)x)[(size_t)(m0 + r) * 48 + f4];
            }
        }
        asm volatile("cp.async.wait_group 0;" ::: "memory");   // B resident
        #pragma unroll
        for (int j = 0; j < 6; j++) {
            int id = j * NT + tid;
            int r = id / 48, f4 = id - r * 48;
            uint32_t h0, l0, h1, l1;
            split2(pf[j].x, pf[j].y, h0, l0);
            split2(pf[j].z, pf[j].w, h1, l1);
            *(uint2*)(sm + r * 100 + 2 * f4)        = make_uint2(h0, h1);
            *(uint2*)(sm + 3200 + r * 100 + 2 * f4) = make_uint2(l0, l1);
        }
        __syncthreads();

        #pragma unroll 1
        for (int i = 0; i < count; i++) {
            const int m0c = (start + i) * 32;
            if (i + 1 < count) {
                int m1 = (start + i + 1) * 32;
                #pragma unroll
                for (int j = 0; j < 6; j++) {
                    int id = j * NT + tid;
                    int r = id / 48, f4 = id - r * 48;
                    pf[j] = ((const float4*)x)[(size_t)(m1 + r) * 48 + f4];
                }
            }
            float acc[6][4];
            #pragma unroll
            for (int a = 0; a < 6; a++)
                #pragma unroll
                for (int b = 0; b < 4; b++) acc[a][b] = 0.f;
            compute_tile(smb, i & 1, wm, wn, aoff, boff, acc);

            // epilogue: bias (+q prescale), store fp32
            #pragma unroll
            for (int n = 0; n < 6; n++) {
                int r = m0c + wm + lr;
                int col = wn + n * 8 + 2 * lc;
                *(float2*)(dst + (size_t)r * DD + col) =
                    make_float2((acc[n][0] + b0r[n]) * scale,
                                (acc[n][1] + b1r[n]) * scale);
                *(float2*)(dst + (size_t)(r + 8) * DD + col) =
                    make_float2((acc[n][2] + b0r[n]) * scale,
                                (acc[n][3] + b1r[n]) * scale);
            }
            if (i + 1 < count) {
                int dstbuf = (i + 1) & 1;
                #pragma unroll
                for (int j = 0; j < 6; j++) {
                    int id = j * NT + tid;
                    int r = id / 48, f4 = id - r * 48;
                    uint32_t h0, l0, h1, l1;
                    split2(pf[j].x, pf[j].y, h0, l0);
                    split2(pf[j].z, pf[j].w, h1, l1);
                    *(uint2*)(sm + dstbuf * A_BUF_W + r * 100 + 2 * f4)        = make_uint2(h0, h1);
                    *(uint2*)(sm + dstbuf * A_BUF_W + 3200 + r * 100 + 2 * f4) = make_uint2(l0, l1);
                }
            }
            __syncthreads();
        }
    }
}

// =====================================================================================
// k_attn: banded attention; writes bf16 hi/lo pair of attn output.
// =====================================================================================
__global__ __launch_bounds__(256) void k_attn(const float* __restrict__ mask0)
{
    int g = blockIdx.x * 256 + threadIdx.x;
    int m = g >> 4;
    int h = g & 15;
    int i = m & (SS - 1);
    int b = m >> 13;

    const float* qp = g_q + (size_t)m * DD + h * 12;
    float q[12];
    #pragma unroll
    for (int j = 0; j < 3; j++) {
        float4 t = *(const float4*)(qp + 4 * j);
        q[4*j] = t.x; q[4*j+1] = t.y; q[4*j+2] = t.z; q[4*j+3] = t.w;
    }

    const float NEGINF = __int_as_float(0xff800000);
    float sc[5];
    bool val[5];
    #pragma unroll
    for (int dd = 0; dd < 5; dd++) {
        int d = dd - 2;
        int ik = i + d;
        bool v = (ik >= 0) && (ik < SS);
        val[dd] = v;
        float s = NEGINF;
        if (v) {
            const float* kp = g_k + (size_t)(m + d) * DD + h * 12;
            float a = 0.f;
            #pragma unroll
            for (int j = 0; j < 3; j++) {
                float4 t = *(const float4*)(kp + 4 * j);
                a += q[4*j] * t.x + q[4*j+1] * t.y + q[4*j+2] * t.z + q[4*j+3] * t.w;
            }
            float mk = mask0[b * SS + ik];
            s = a + ((mk != 0.f) ? -3.402823466e38f : 0.f);
        }
        sc[dd] = s;
    }
    float mx = sc[0];
    #pragma unroll
    for (int dd = 1; dd < 5; dd++) mx = fmaxf(mx, sc[dd]);
    float p[5], sum = 0.f;
    #pragma unroll
    for (int dd = 0; dd < 5; dd++) { p[dd] = __expf(sc[dd] - mx); sum += p[dd]; }
    float inv = 1.f / sum;
    if (mask0[b * SS + i] < 0.f) inv = 0.f;

    float ctx[12];
    #pragma unroll
    for (int j = 0; j < 12; j++) ctx[j] = 0.f;
    #pragma unroll
    for (int dd = 0; dd < 5; dd++) {
        if (val[dd]) {
            const float* vp = g_v + (size_t)(m + dd - 2) * DD + h * 12;
            #pragma unroll
            for (int j = 0; j < 3; j++) {
                float4 t = *(const float4*)(vp + 4 * j);
                ctx[4*j]   += p[dd] * t.x;
                ctx[4*j+1] += p[dd] * t.y;
                ctx[4*j+2] += p[dd] * t.z;
                ctx[4*j+3] += p[dd] * t.w;
            }
        }
    }
    size_t ow = (size_t)m * 96 + h * 6;
    #pragma unroll
    for (int j = 0; j < 6; j++) {
        uint32_t hw, lw;
        split2(ctx[2*j] * inv, ctx[2*j+1] * inv, hw, lw);
        g_ah[ow + j] = hw;
        g_al[ow + j] = lw;
    }
}

// =====================================================================================
// k_out: persistent. Wo resident; 32-row A tiles (pre-split, cp.async double-buffer);
// register-resident LN epilogue via quad-shfl + tiny smem cross-warp reduce.
// =====================================================================================
__device__ __forceinline__ void stage_A_out(uint32_t smb, int tid, int m0, int buf)
{
    #pragma unroll
    for (int j = 0; j < 6; j++) {
        int id = j * NT + tid;                 // < 1536
        int half = id >= 768;
        int j2 = id - (half ? 768 : 0);
        int r = j2 / 24, u = j2 - r * 24;
        const uint32_t* src = (half ? g_al : g_ah) + (size_t)(m0 + r) * 96 + u * 4;
        cpa16(smb + (buf * A_BUF_W + half * 3200 + r * 100 + u * 4) * 4, src);
    }
    asm volatile("cp.async.commit_group;");
}

__global__ __launch_bounds__(NT, 1) void k_out(
    const float* __restrict__ x, const float* __restrict__ bo,
    const float* __restrict__ lng, const float* __restrict__ lnb,
    float* __restrict__ out)
{
    extern __shared__ __align__(16) uint32_t sm[];
    float* red = (float*)(sm + RED_W);
    const uint32_t smb = (uint32_t)__cvta_generic_to_shared(sm);
    const int tid = threadIdx.x;
    const int warp = tid >> 5, lane = tid & 31;
    const int group = lane >> 3, lrow = lane & 7;
    const int wm = (warp >> 2) * 16, wn = (warp & 3) * 48;
    const int nw = warp & 3;
    const int lr = lane >> 2, lc = lane & 3;
    const int aoff = (lrow + ((group & 1) << 3)) * 100 + ((group >> 1) << 2);
    const int boff = (lrow + ((group >> 1) << 3)) * 100 + ((group & 1) << 2);

    int start, count;
    tile_range(blockIdx.x, start, count);

    // per-thread column constants
    float bo0[6], bo1[6], lg0[6], lg1[6], lb0[6], lb1[6];
    #pragma unroll
    for (int n = 0; n < 6; n++) {
        int col = wn + n * 8 + 2 * lc;
        bo0[n] = __ldg(bo + col);  bo1[n] = __ldg(bo + col + 1);
        lg0[n] = __ldg(lng + col); lg1[n] = __ldg(lng + col + 1);
        lb0[n] = __ldg(lnb + col); lb1[n] = __ldg(lnb + col + 1);
    }

    stage_B_resident(smb, tid, g_wh + 3 * 18432, g_wl + 3 * 18432);
    stage_A_out(smb, tid, start * 32, 0);

    #pragma unroll 1
    for (int i = 0; i < count; i++) {
        const int m0c = (start + i) * 32;
        if (i + 1 < count) stage_A_out(smb, tid, (start + i + 1) * 32, (i + 1) & 1);
        if (i + 1 < count) asm volatile("cp.async.wait_group 1;" ::: "memory");
        else               asm volatile("cp.async.wait_group 0;" ::: "memory");
        __syncthreads();

        float acc[6][4];
        #pragma unroll
        for (int a = 0; a < 6; a++)
            #pragma unroll
            for (int b = 0; b < 4; b++) acc[a][b] = 0.f;
        compute_tile(smb, i & 1, wm, wn, aoff, boff, acc);

        // h = acc + bo + x  (two rows per thread: r0, r0+8)
        const int r0 = wm + lr;
        const int grow0 = m0c + r0, grow1 = grow0 + 8;
        float h00[6], h01[6], h10[6], h11[6];
        float s0 = 0.f, q0 = 0.f, s1 = 0.f, q1 = 0.f;
        #pragma unroll
        for (int n = 0; n < 6; n++) {
            int col = wn + n * 8 + 2 * lc;
            float2 xv0 = *(const float2*)(x + (size_t)grow0 * DD + col);
            float2 xv1 = *(const float2*)(x + (size_t)grow1 * DD + col);
            h00[n] = acc[n][0] + bo0[n] + xv0.x;
            h01[n] = acc[n][1] + bo1[n] + xv0.y;
            h10[n] = acc[n][2] + bo0[n] + xv1.x;
            h11[n] = acc[n][3] + bo1[n] + xv1.y;
            s0 += h00[n] + h01[n];
            q0 += h00[n] * h00[n] + h01[n] * h01[n];
            s1 += h10[n] + h11[n];
            q1 += h10[n] * h10[n] + h11[n] * h11[n];
        }
        // reduce over lc (lanes lr*4 + lc): xor 1, 2
        #pragma unroll
        for (int o = 1; o <= 2; o <<= 1) {
            s0 += __shfl_xor_sync(0xffffffffu, s0, o);
            q0 += __shfl_xor_sync(0xffffffffu, q0, o);
            s1 += __shfl_xor_sync(0xffffffffu, s1, o);
            q1 += __shfl_xor_sync(0xffffffffu, q1, o);
        }
        if (lc == 0) {
            red[(r0 * 4 + nw) * 2]           = s0;
            red[(r0 * 4 + nw) * 2 + 1]       = q0;
            red[((r0 + 8) * 4 + nw) * 2]     = s1;
            red[((r0 + 8) * 4 + nw) * 2 + 1] = q1;
        }
        __syncthreads();
        float S0 = 0.f, Q0 = 0.f, S1 = 0.f, Q1 = 0.f;
        #pragma unroll
        for (int j = 0; j < 4; j++) {
            S0 += red[(r0 * 4 + j) * 2];
            Q0 += red[(r0 * 4 + j) * 2 + 1];
            S1 += red[((r0 + 8) * 4 + j) * 2];
            Q1 += red[((r0 + 8) * 4 + j) * 2 + 1];
        }
        float mu0 = S0 * (1.f / 192.f);
        float rs0 = rsqrtf(fmaxf(Q0 * (1.f / 192.f) - mu0 * mu0, 0.f) + 1e-12f);
        float mu1 = S1 * (1.f / 192.f);
        float rs1 = rsqrtf(fmaxf(Q1 * (1.f / 192.f) - mu1 * mu1, 0.f) + 1e-12f);
        #pragma unroll
        for (int n = 0; n < 6; n++) {
            int col = wn + n * 8 + 2 * lc;
            *(float2*)(out + (size_t)grow0 * DD + col) =
                make_float2((h00[n] - mu0) * rs0 * lg0[n] + lb0[n],
                            (h01[n] - mu0) * rs0 * lg1[n] + lb1[n]);
            *(float2*)(out + (size_t)grow1 * DD + col) =
                make_float2((h10[n] - mu1) * rs1 * lg0[n] + lb0[n],
                            (h11[n] - mu1) * rs1 * lg1[n] + lb1[n]);
        }
        __syncthreads();   // red + A buffer safe to reuse
    }
}

// =====================================================================================
extern "C" void kernel_launch(void* const* d_in, const int* in_sizes, int n_in,
                              void* d_out, int out_size)
{
    const float* x    = (const float*)d_in[0];
    const float* mask0= (const float*)d_in[1];
    const float* Wq   = (const float*)d_in[2];
    const float* bq   = (const float*)d_in[3];
    const float* Wk   = (const float*)d_in[4];
    const float* bk   = (const float*)d_in[5];
    const float* Wv   = (const float*)d_in[6];
    const float* bv   = (const float*)d_in[7];
    const float* Wo   = (const float*)d_in[8];
    const float* bo   = (const float*)d_in[9];
    const float* lng  = (const float*)d_in[10];
    const float* lnb  = (const float*)d_in[11];
    float* out = (float*)d_out;

    cudaFuncSetAttribute(k_qkv, cudaFuncAttributeMaxDynamicSharedMemorySize, QKV_SMEM);
    cudaFuncSetAttribute(k_out, cudaFuncAttributeMaxDynamicSharedMemorySize, OUT_SMEM);

    k_split_w<<<144, 256>>>(Wq, Wk, Wv, Wo);
    k_qkv<<<NCTA, NT, QKV_SMEM>>>(x, bq, bk, bv);
    k_attn<<<(MTOT * 16) / 256, 256>>>(mask0);
    k_out<<<NCTA, NT, OUT_SMEM>>>(x, bo, lng, lnb, out);
}